// round 2
// baseline (speedup 1.0000x reference)
#include <cuda_runtime.h>
#include <cfloat>
#include <math.h>

#define EMBD 128
#define NMAX 100000
#define EMAX 400000
#define GMAXC 4096
#define LN2F 0.69314718055994530942f

// ---------------- scratch (static __device__, no allocation) ----------------
__device__ float g_Ha[(size_t)NMAX * EMBD];
__device__ float g_Hb[(size_t)NMAX * EMBD];
__device__ float g_T1[(size_t)NMAX * EMBD];
__device__ float g_T2[(size_t)NMAX * EMBD];
__device__ float g_A [(size_t)NMAX * EMBD];
__device__ float g_B [(size_t)NMAX * EMBD];
__device__ int   g_deg[NMAX];
__device__ int   g_rowptr[NMAX + 1];
__device__ int   g_cursor[NMAX];
__device__ int   g_eids[EMAX];
__device__ int   g_gs[GMAXC];
__device__ int   g_ge[GMAXC];
__device__ float g_cvec[EMBD];
__device__ float g_bsum[EMBD];
__device__ int   g_bsums[256];

// ---------------- helpers ----------------
__device__ __forceinline__ float spf(float x) {
    // numerically stable softplus, matches jax.nn.softplus
    return fmaxf(x, 0.0f) + log1pf(expf(-fabsf(x)));
}
__device__ __forceinline__ float4 sp4(float4 v) {
    v.x = spf(v.x); v.y = spf(v.y); v.z = spf(v.z); v.w = spf(v.w); return v;
}
__device__ __forceinline__ float4 add4(float4 a, float4 b) {
    a.x += b.x; a.y += b.y; a.z += b.z; a.w += b.w; return a;
}
__device__ __forceinline__ float4 max4(float4 a, float4 b) {
    a.x = fmaxf(a.x, b.x); a.y = fmaxf(a.y, b.y);
    a.z = fmaxf(a.z, b.z); a.w = fmaxf(a.w, b.w); return a;
}

// ---------------- setup kernels ----------------
__global__ void k_init(int N, int G) {
    int i = blockIdx.x * blockDim.x + threadIdx.x;
    if (i < N) g_deg[i] = 0;
    if (i < G) { g_gs[i] = 0; g_ge[i] = 0; }
}

__global__ void k_deg(const int* __restrict__ dst, int E) {
    int e = blockIdx.x * blockDim.x + threadIdx.x;
    if (e < E) atomicAdd(&g_deg[dst[e]], 1);
}

// inclusive scan per 1024-block
__global__ void k_scan1(int N) {
    __shared__ int sh[1024];
    int i = blockIdx.x * 1024 + threadIdx.x;
    int v = (i < N) ? g_deg[i] : 0;
    sh[threadIdx.x] = v;
    __syncthreads();
    for (int off = 1; off < 1024; off <<= 1) {
        int t = (threadIdx.x >= off) ? sh[threadIdx.x - off] : 0;
        __syncthreads();
        sh[threadIdx.x] += t;
        __syncthreads();
    }
    if (i < N) g_rowptr[i + 1] = sh[threadIdx.x];
    if (threadIdx.x == 1023) g_bsums[blockIdx.x] = sh[1023];
}

__global__ void k_scan2(int nb) {
    if (threadIdx.x == 0 && blockIdx.x == 0) {
        int acc = 0;
        for (int b = 0; b < nb; b++) { int t = g_bsums[b]; g_bsums[b] = acc; acc += t; }
    }
}

__global__ void k_scan3(int N) {
    int i = blockIdx.x * blockDim.x + threadIdx.x;
    if (i == 0) g_rowptr[0] = 0;
    if (i < N) g_rowptr[i + 1] += g_bsums[i >> 10];
}

__global__ void k_cursor(int N) {
    int i = blockIdx.x * blockDim.x + threadIdx.x;
    if (i < N) g_cursor[i] = g_rowptr[i];
}

__global__ void k_fill(const int* __restrict__ dst, int E) {
    int e = blockIdx.x * blockDim.x + threadIdx.x;
    if (e < E) {
        int p = atomicAdd(&g_cursor[dst[e]], 1);
        g_eids[p] = e;
    }
}

// h_a = sp(emb_atom[x_ids]); Hb_node = sp(emb_bond[edge_attr_ids[0..N)])
__global__ void k_embed(const int* __restrict__ xids, const int* __restrict__ eattr,
                        const float* __restrict__ embA, const float* __restrict__ embB,
                        int N) {
    int idx = blockIdx.x * blockDim.x + threadIdx.x;
    if (idx >= N * 32) return;
    int n = idx >> 5, c = idx & 31;
    float4 va = __ldg((const float4*)(embA + (size_t)xids[n] * EMBD) + c);
    ((float4*)(g_Ha + (size_t)n * EMBD))[c] = sp4(va);
    float4 vb = __ldg((const float4*)(embB + (size_t)eattr[n] * EMBD) + c);
    ((float4*)(g_Hb + (size_t)n * EMBD))[c] = sp4(vb);
}

// cvec = ln2 * colsum(W_edge); bsum = b_msg + b_edge
__global__ void k_prep(const float* __restrict__ W_edge,
                       const float* __restrict__ bm, const float* __restrict__ be) {
    int c = threadIdx.x;
    float s = 0.0f;
    for (int k = 0; k < EMBD; k++) s += W_edge[k * EMBD + c];
    g_cvec[c] = LN2F * s;
    g_bsum[c] = bm[c] + be[c];
}

// ---------------- GEMM: Y[rows,128] = X[rows,128] @ W + bias ----------------
// W row-major [128,128]. 256 threads = 8 warps; warp computes 4 rows, lane = 4 cols.
__global__ void gemm128(const float* __restrict__ X, int rows,
                        const float* __restrict__ W,
                        const float* __restrict__ bias,
                        float* __restrict__ Y) {
    extern __shared__ float sm[];
    float* Wsh = sm;               // 128*128 floats
    float* Xsh = sm + 16384;       // 8 warps * 4 rows * 128
    int tid = threadIdx.x;

    const float4* W4 = (const float4*)W;
    float4* Wsh4 = (float4*)Wsh;
    for (int i = tid; i < 4096; i += 256) Wsh4[i] = W4[i];
    __syncthreads();

    int warp = tid >> 5, lane = tid & 31;
    float4 bia = make_float4(0.f, 0.f, 0.f, 0.f);
    if (bias) bia = ((const float4*)bias)[lane];
    float* xw = Xsh + warp * 512;
    int stride = gridDim.x * 8;

    for (int rg = blockIdx.x * 8 + warp; rg * 4 < rows; rg += stride) {
        int r0 = rg * 4;
        int nr = rows - r0; if (nr > 4) nr = 4;
        __syncwarp();
        for (int r = 0; r < nr; r++)
            ((float4*)(xw + r * 128))[lane] =
                ((const float4*)(X + (size_t)(r0 + r) * EMBD))[lane];
        __syncwarp();

        float4 a0 = bia, a1 = bia, a2 = bia, a3 = bia;
        #pragma unroll 4
        for (int k = 0; k < 128; k++) {
            float4 w = ((float4*)(Wsh + k * 128))[lane];
            float x0 = xw[k];
            float x1 = xw[128 + k];
            float x2 = xw[256 + k];
            float x3 = xw[384 + k];
            a0.x += w.x * x0; a0.y += w.y * x0; a0.z += w.z * x0; a0.w += w.w * x0;
            a1.x += w.x * x1; a1.y += w.y * x1; a1.z += w.z * x1; a1.w += w.w * x1;
            a2.x += w.x * x2; a2.y += w.y * x2; a2.z += w.z * x2; a2.w += w.w * x2;
            a3.x += w.x * x3; a3.y += w.y * x3; a3.z += w.z * x3; a3.w += w.w * x3;
        }
        ((float4*)(Y + (size_t)r0 * EMBD))[lane] = a0;
        if (nr > 1) ((float4*)(Y + (size_t)(r0 + 1) * EMBD))[lane] = a1;
        if (nr > 2) ((float4*)(Y + (size_t)(r0 + 2) * EMBD))[lane] = a2;
        if (nr > 3) ((float4*)(Y + (size_t)(r0 + 3) * EMBD))[lane] = a3;
    }
}

// ---------------- dual GEMM: Ya = X@(Wa-Wsub)+biasA ; Yb = X@Wb (same X) ----------------
// smem: Wa' (64KB) + Wb (64KB) + X staging (16KB) = 144KB -> 1 CTA/SM
__global__ void gemm128_dual(const float* __restrict__ X, int rows,
                             const float* __restrict__ Wa, const float* __restrict__ Wsub,
                             const float* __restrict__ biasA, float* __restrict__ Ya,
                             const float* __restrict__ Wb, float* __restrict__ Yb) {
    extern __shared__ float sm[];
    float* WshA = sm;                 // 16384 floats
    float* WshB = sm + 16384;         // 16384 floats
    float* Xsh  = sm + 32768;         // 8 * 512 floats
    int tid = threadIdx.x;

    {
        const float4* Wa4 = (const float4*)Wa;
        const float4* Ws4 = (const float4*)Wsub;
        const float4* Wb4 = (const float4*)Wb;
        float4* A4 = (float4*)WshA;
        float4* B4 = (float4*)WshB;
        for (int i = tid; i < 4096; i += 256) {
            float4 a = Wa4[i], s = Ws4[i];
            a.x -= s.x; a.y -= s.y; a.z -= s.z; a.w -= s.w;
            A4[i] = a;
            B4[i] = Wb4[i];
        }
    }
    __syncthreads();

    int warp = tid >> 5, lane = tid & 31;
    float4 bia = ((const float4*)biasA)[lane];
    float* xw = Xsh + warp * 512;
    int stride = gridDim.x * 8;

    for (int rg = blockIdx.x * 8 + warp; rg * 4 < rows; rg += stride) {
        int r0 = rg * 4;
        int nr = rows - r0; if (nr > 4) nr = 4;
        __syncwarp();
        for (int r = 0; r < nr; r++)
            ((float4*)(xw + r * 128))[lane] =
                ((const float4*)(X + (size_t)(r0 + r) * EMBD))[lane];
        __syncwarp();

        float4 a0 = bia, a1 = bia, a2 = bia, a3 = bia;
        float4 b0 = make_float4(0,0,0,0), b1 = b0, b2 = b0, b3 = b0;
        #pragma unroll 2
        for (int k = 0; k < 128; k++) {
            float4 wa = ((float4*)(WshA + k * 128))[lane];
            float4 wb = ((float4*)(WshB + k * 128))[lane];
            float x0 = xw[k];
            float x1 = xw[128 + k];
            float x2 = xw[256 + k];
            float x3 = xw[384 + k];
            a0.x += wa.x * x0; a0.y += wa.y * x0; a0.z += wa.z * x0; a0.w += wa.w * x0;
            a1.x += wa.x * x1; a1.y += wa.y * x1; a1.z += wa.z * x1; a1.w += wa.w * x1;
            a2.x += wa.x * x2; a2.y += wa.y * x2; a2.z += wa.z * x2; a2.w += wa.w * x2;
            a3.x += wa.x * x3; a3.y += wa.y * x3; a3.z += wa.z * x3; a3.w += wa.w * x3;
            b0.x += wb.x * x0; b0.y += wb.y * x0; b0.z += wb.z * x0; b0.w += wb.w * x0;
            b1.x += wb.x * x1; b1.y += wb.y * x1; b1.z += wb.z * x1; b1.w += wb.w * x1;
            b2.x += wb.x * x2; b2.y += wb.y * x2; b2.z += wb.z * x2; b2.w += wb.w * x2;
            b3.x += wb.x * x3; b3.y += wb.y * x3; b3.z += wb.z * x3; b3.w += wb.w * x3;
        }
        ((float4*)(Ya + (size_t)r0 * EMBD))[lane] = a0;
        ((float4*)(Yb + (size_t)r0 * EMBD))[lane] = b0;
        if (nr > 1) { ((float4*)(Ya + (size_t)(r0+1) * EMBD))[lane] = a1;
                      ((float4*)(Yb + (size_t)(r0+1) * EMBD))[lane] = b1; }
        if (nr > 2) { ((float4*)(Ya + (size_t)(r0+2) * EMBD))[lane] = a2;
                      ((float4*)(Yb + (size_t)(r0+2) * EMBD))[lane] = b2; }
        if (nr > 3) { ((float4*)(Ya + (size_t)(r0+3) * EMBD))[lane] = a3;
                      ((float4*)(Yb + (size_t)(r0+3) * EMBD))[lane] = b3; }
    }
}

// ---------------- EdgeConv pull: Hb[j] = sp(T1[j] + max_e T2[src[e]]), else ln2 ----------------
__global__ void k_edgeconv(const int* __restrict__ srcA, int N, float* __restrict__ hbOut) {
    int w = (blockIdx.x * blockDim.x + threadIdx.x) >> 5;
    int lane = threadIdx.x & 31;
    if (w >= N) return;
    int j = w;
    int s0 = g_rowptr[j], s1 = g_rowptr[j + 1];
    float4 out;
    if (s1 > s0) {
        float4 m = make_float4(-FLT_MAX, -FLT_MAX, -FLT_MAX, -FLT_MAX);
        for (int i = s0; i < s1; i++) {
            int e = __ldg(g_eids + i);
            int sn = __ldg(srcA + e);
            float4 v = __ldg((const float4*)(g_T2 + (size_t)sn * EMBD) + lane);
            m = max4(m, v);
        }
        float4 t = ((const float4*)(g_T1 + (size_t)j * EMBD))[lane]; // includes b_bond
        out = sp4(add4(t, m));
    } else {
        out = make_float4(LN2F, LN2F, LN2F, LN2F);
    }
    ((float4*)(g_Hb + (size_t)j * EMBD))[lane] = out;
    if (hbOut) ((float4*)(hbOut + (size_t)j * EMBD))[lane] = out;
}

// ---------------- GeneralConv pull: Ha[j] = sp(sum_e(A[src]+Bv(e)) + deg*bsum + Ha[j]) ----------------
__global__ void k_genconv(const int* __restrict__ srcA, int N, float* __restrict__ haOut) {
    int w = (blockIdx.x * blockDim.x + threadIdx.x) >> 5;
    int lane = threadIdx.x & 31;
    if (w >= N) return;
    int j = w;
    int s0 = g_rowptr[j], s1 = g_rowptr[j + 1];
    float4 s = make_float4(0.f, 0.f, 0.f, 0.f);
    float4 cv = ((const float4*)g_cvec)[lane];
    for (int i = s0; i < s1; i++) {
        int e = __ldg(g_eids + i);
        int sn = __ldg(srcA + e);
        float4 a = __ldg((const float4*)(g_A + (size_t)sn * EMBD) + lane);
        float4 b = (e < N) ? __ldg((const float4*)(g_B + (size_t)e * EMBD) + lane) : cv;
        s = add4(s, add4(a, b));
    }
    float degf = (float)(s1 - s0);
    float4 bs = ((const float4*)g_bsum)[lane];
    float4 h = ((float4*)(g_Ha + (size_t)j * EMBD))[lane];
    s.x += degf * bs.x + h.x; s.y += degf * bs.y + h.y;
    s.z += degf * bs.z + h.z; s.w += degf * bs.w + h.w;
    float4 out = sp4(s);
    ((float4*)(g_Ha + (size_t)j * EMBD))[lane] = out;
    if (haOut) ((float4*)(haOut + (size_t)j * EMBD))[lane] = out;
}

// ---------------- constant tail of h_b output (rows >= N are all ln2) ----------------
__global__ void k_tail(float* __restrict__ outHb, int N, int E) {
    size_t idx = (size_t)blockIdx.x * blockDim.x + threadIdx.x;
    size_t tot = (size_t)(E - N) * 32;
    if (idx >= tot) return;
    float4* p = (float4*)(outHb + (size_t)N * EMBD);
    p[idx] = make_float4(LN2F, LN2F, LN2F, LN2F);
}

// ---------------- graph boundaries (batch is sorted) ----------------
__global__ void k_bounds(const int* __restrict__ batch, int N) {
    int n = blockIdx.x * blockDim.x + threadIdx.x;
    if (n >= N) return;
    int b = batch[n];
    if (n == 0 || batch[n - 1] != b) g_gs[b] = n;
    if (n == N - 1 || batch[n + 1] != b) g_ge[b] = n + 1;
}

// ---------------- pooling + readout MLP, one block (128 thr) per graph ----------------
__global__ void k_readout(const float* __restrict__ Wr1, const float* __restrict__ br1,
                          const float* __restrict__ Wr2, const float* __restrict__ br2,
                          const float* __restrict__ Wr3, const float* __restrict__ br3,
                          float* __restrict__ out) {
    __shared__ float ps[128];
    __shared__ float h1[64];
    __shared__ float h2[64];
    __shared__ float red[64];
    int g = blockIdx.x, c = threadIdx.x;
    int s = g_gs[g], e = g_ge[g];
    float acc = 0.0f;
    for (int n = s; n < e; n++) acc += g_Ha[(size_t)n * EMBD + c];
    ps[c] = acc;
    __syncthreads();
    if (c < 64) {
        float v = br1[c];
        #pragma unroll 8
        for (int k = 0; k < 128; k++) v += ps[k] * __ldg(Wr1 + k * 64 + c);
        h1[c] = spf(v);
    }
    __syncthreads();
    if (c < 64) {
        float v = br2[c];
        #pragma unroll 8
        for (int k = 0; k < 64; k++) v += h1[k] * __ldg(Wr2 + k * 64 + c);
        h2[c] = spf(v);
    }
    __syncthreads();
    if (c < 64) red[c] = h2[c] * __ldg(Wr3 + c);
    __syncthreads();
    if (c == 0) {
        float o = br3[0];
        for (int k = 0; k < 64; k++) o += red[k];
        out[g] = o;
    }
}

// ---------------- host launch ----------------
extern "C" void kernel_launch(void* const* d_in, const int* in_sizes, int n_in,
                              void* d_out_, int out_size) {
    const int*   x_ids    = (const int*)d_in[0];
    const int*   eattr    = (const int*)d_in[1];
    const int*   eidx     = (const int*)d_in[2];
    const int*   batch    = (const int*)d_in[3];
    const float* emb_atom = (const float*)d_in[4];
    const float* emb_bond = (const float*)d_in[5];
    const float* W_bond   = (const float*)d_in[6];
    const float* b_bond   = (const float*)d_in[7];
    const float* W_msg    = (const float*)d_in[8];
    const float* b_msg    = (const float*)d_in[9];
    const float* W_edge   = (const float*)d_in[10];
    const float* b_edge   = (const float*)d_in[11];
    const float* W_r1     = (const float*)d_in[12];
    const float* b_r1     = (const float*)d_in[13];
    const float* W_r2     = (const float*)d_in[14];
    const float* b_r2     = (const float*)d_in[15];
    const float* W_r3     = (const float*)d_in[16];
    const float* b_r3     = (const float*)d_in[17];

    int N = in_sizes[0];
    int E = in_sizes[1];
    if (N > NMAX || E > EMAX || N < 1 || E < N) return;

    float* d_out = (float*)d_out_;
    long long rest = (long long)out_size - (long long)EMBD * ((long long)N + (long long)E);
    int G;
    float* outHa = nullptr;
    float* outHb = nullptr;
    if (rest > 0) {
        G = (int)rest;
        outHa = d_out + G;
        outHb = d_out + (size_t)G + (size_t)N * EMBD;
    } else {
        G = out_size;
    }
    if (G > GMAXC) return;

    const int* srcA = eidx;
    const int* dstA = eidx + E;

    float *pHa, *pHb, *pT1, *pT2, *pA, *pB;
    cudaGetSymbolAddress((void**)&pHa, g_Ha);
    cudaGetSymbolAddress((void**)&pHb, g_Hb);
    cudaGetSymbolAddress((void**)&pT1, g_T1);
    cudaGetSymbolAddress((void**)&pT2, g_T2);
    cudaGetSymbolAddress((void**)&pA,  g_A);
    cudaGetSymbolAddress((void**)&pB,  g_B);

    const int SMEM_GEMM  = 128 * 128 * 4 + 8 * 4 * 128 * 4;          // 81920
    const int SMEM_DUAL  = 2 * 128 * 128 * 4 + 8 * 4 * 128 * 4;      // 147456
    cudaFuncSetAttribute(gemm128, cudaFuncAttributeMaxDynamicSharedMemorySize, SMEM_GEMM);
    cudaFuncSetAttribute(gemm128_dual, cudaFuncAttributeMaxDynamicSharedMemorySize, SMEM_DUAL);

    int mNG = (N > G) ? N : G;
    k_init<<<(mNG + 255) / 256, 256>>>(N, G);
    k_deg<<<(E + 255) / 256, 256>>>(dstA, E);
    int nb = (N + 1023) / 1024;
    k_scan1<<<nb, 1024>>>(N);
    k_scan2<<<1, 32>>>(nb);
    k_scan3<<<(N + 255) / 256, 256>>>(N);
    k_cursor<<<(N + 255) / 256, 256>>>(N);
    k_fill<<<(E + 255) / 256, 256>>>(dstA, E);
    k_embed<<<(N * 32 + 255) / 256, 256>>>(x_ids, eattr, emb_atom, emb_bond, N);
    k_prep<<<1, 128>>>(W_edge, b_msg, b_edge);

    const float* W1 = W_bond;                 // rows 0..127 (x_i part)
    const float* W2 = W_bond + EMBD * EMBD;   // rows 128..255 (x_j - x_i part)

    const int GEMM_GRID = 296;
    const int DUAL_GRID = 148;
    int warpBlocks = (N * 32 + 255) / 256;

    for (int it = 0; it < 2; it++) {
        bool last = (it == 1);
        // T1 = Hb @ (W1 - W2) + b_bond ; T2 = Hb @ W2   (fused, shared X reads)
        gemm128_dual<<<DUAL_GRID, 256, SMEM_DUAL>>>(pHb, N, W1, W2, b_bond, pT1, W2, pT2);
        k_edgeconv<<<warpBlocks, 256>>>(srcA, N, last ? outHb : nullptr);
        // B = Hb_new @ W_edge ; A = Ha_old @ W_msg
        gemm128<<<GEMM_GRID, 256, SMEM_GEMM>>>(pHb, N, W_edge, nullptr, pB);
        gemm128<<<GEMM_GRID, 256, SMEM_GEMM>>>(pHa, N, W_msg, nullptr, pA);
        k_genconv<<<warpBlocks, 256>>>(srcA, N, last ? outHa : nullptr);
    }

    if (outHb && E > N) {
        size_t tot = (size_t)(E - N) * 32;
        k_tail<<<(int)((tot + 255) / 256), 256>>>(outHb, N, E);
    }
    k_bounds<<<(N + 255) / 256, 256>>>(batch, N);
    k_readout<<<G, 128>>>(W_r1, b_r1, W_r2, b_r2, W_r3, b_r3, d_out);
}

// round 10
// speedup vs baseline: 1.5289x; 1.5289x over previous
#include <cuda_runtime.h>
#include <cuda_bf16.h>
#include <cfloat>
#include <math.h>
#include <cstdint>

#define EMBD 128
#define NMAX 100000
#define EMAX 400000
#define GMAXC 4096
#define LN2F 0.69314718055994530942f
#define WSTRIDE 136   // bf16 elems per smem row: 128 + 8 pad (272 B) -> conflict-free B frags

// ---------------- scratch (static __device__, no allocation) ----------------
__device__ float g_Ha[(size_t)NMAX * EMBD];
__device__ float g_Hb[(size_t)NMAX * EMBD];
__device__ float g_T1[(size_t)NMAX * EMBD];
__device__ float g_T2[(size_t)NMAX * EMBD];
__device__ float g_A [(size_t)NMAX * EMBD];
__device__ float g_B [(size_t)NMAX * EMBD];
__device__ float g_Wm[EMBD * EMBD];          // W1 - W2 precomputed
__device__ int   g_deg[NMAX];
__device__ int   g_rowptr[NMAX + 1];
__device__ int   g_cursor[NMAX];
__device__ int   g_eids[EMAX];
__device__ int   g_gs[GMAXC];
__device__ int   g_ge[GMAXC];
__device__ float g_cvec[EMBD];
__device__ float g_bsum[EMBD];
__device__ int   g_bsums[256];

// ---------------- math helpers ----------------
__device__ __forceinline__ float spf(float x) {
    return fmaxf(x, 0.0f) + log1pf(expf(-fabsf(x)));
}
__device__ __forceinline__ float4 sp4(float4 v) {
    v.x = spf(v.x); v.y = spf(v.y); v.z = spf(v.z); v.w = spf(v.w); return v;
}
__device__ __forceinline__ float4 add4(float4 a, float4 b) {
    a.x += b.x; a.y += b.y; a.z += b.z; a.w += b.w; return a;
}
__device__ __forceinline__ float4 max4(float4 a, float4 b) {
    a.x = fmaxf(a.x, b.x); a.y = fmaxf(a.y, b.y);
    a.z = fmaxf(a.z, b.z); a.w = fmaxf(a.w, b.w); return a;
}

// pack a float2 into bf16x2 hi + bf16x2 lo (residual)
__device__ __forceinline__ void pack2(float2 f, uint32_t& h, uint32_t& l) {
    __nv_bfloat16 h0 = __float2bfloat16(f.x), h1 = __float2bfloat16(f.y);
    __nv_bfloat162 hh = __halves2bfloat162(h0, h1);
    __nv_bfloat162 ll = __floats2bfloat162_rn(f.x - __bfloat162float(h0),
                                              f.y - __bfloat162float(h1));
    h = *(uint32_t*)&hh;
    l = *(uint32_t*)&ll;
}

__device__ __forceinline__ void mma16816(float& c0, float& c1, float& c2, float& c3,
                                         uint32_t a0, uint32_t a1, uint32_t a2, uint32_t a3,
                                         uint32_t b0, uint32_t b1) {
    asm volatile(
        "mma.sync.aligned.m16n8k16.row.col.f32.bf16.bf16.f32 "
        "{%0,%1,%2,%3}, {%4,%5,%6,%7}, {%8,%9}, {%0,%1,%2,%3};"
        : "+f"(c0), "+f"(c1), "+f"(c2), "+f"(c3)
        : "r"(a0), "r"(a1), "r"(a2), "r"(a3), "r"(b0), "r"(b1));
}

// ---------------- setup kernels ----------------
__global__ void k_init(int N, int G) {
    int i = blockIdx.x * blockDim.x + threadIdx.x;
    if (i < N) g_deg[i] = 0;
    if (i < G) { g_gs[i] = 0; g_ge[i] = 0; }
}

__global__ void k_deg(const int* __restrict__ dst, int E) {
    int e = blockIdx.x * blockDim.x + threadIdx.x;
    if (e < E) atomicAdd(&g_deg[dst[e]], 1);
}

__global__ void k_scan1(int N) {
    __shared__ int sh[1024];
    int i = blockIdx.x * 1024 + threadIdx.x;
    int v = (i < N) ? g_deg[i] : 0;
    sh[threadIdx.x] = v;
    __syncthreads();
    for (int off = 1; off < 1024; off <<= 1) {
        int t = (threadIdx.x >= off) ? sh[threadIdx.x - off] : 0;
        __syncthreads();
        sh[threadIdx.x] += t;
        __syncthreads();
    }
    if (i < N) g_rowptr[i + 1] = sh[threadIdx.x];
    if (threadIdx.x == 1023) g_bsums[blockIdx.x] = sh[1023];
}

__global__ void k_scan2(int nb) {
    if (threadIdx.x == 0 && blockIdx.x == 0) {
        int acc = 0;
        for (int b = 0; b < nb; b++) { int t = g_bsums[b]; g_bsums[b] = acc; acc += t; }
    }
}

__global__ void k_scan3(int N) {
    int i = blockIdx.x * blockDim.x + threadIdx.x;
    if (i == 0) g_rowptr[0] = 0;
    if (i < N) g_rowptr[i + 1] += g_bsums[i >> 10];
}

__global__ void k_cursor(int N) {
    int i = blockIdx.x * blockDim.x + threadIdx.x;
    if (i < N) g_cursor[i] = g_rowptr[i];
}

__global__ void k_fill(const int* __restrict__ dst, int E) {
    int e = blockIdx.x * blockDim.x + threadIdx.x;
    if (e < E) {
        int p = atomicAdd(&g_cursor[dst[e]], 1);
        g_eids[p] = e;
    }
}

__global__ void k_embed(const int* __restrict__ xids, const int* __restrict__ eattr,
                        const float* __restrict__ embA, const float* __restrict__ embB,
                        int N) {
    int idx = blockIdx.x * blockDim.x + threadIdx.x;
    if (idx >= N * 32) return;
    int n = idx >> 5, c = idx & 31;
    float4 va = __ldg((const float4*)(embA + (size_t)xids[n] * EMBD) + c);
    ((float4*)(g_Ha + (size_t)n * EMBD))[c] = sp4(va);
    float4 vb = __ldg((const float4*)(embB + (size_t)eattr[n] * EMBD) + c);
    ((float4*)(g_Hb + (size_t)n * EMBD))[c] = sp4(vb);
}

__global__ void k_prep(const float* __restrict__ W_edge,
                       const float* __restrict__ bm, const float* __restrict__ be) {
    int c = threadIdx.x;
    float s = 0.0f;
    for (int k = 0; k < EMBD; k++) s += W_edge[k * EMBD + c];
    g_cvec[c] = LN2F * s;
    g_bsum[c] = bm[c] + be[c];
}

__global__ void k_wprep(const float* __restrict__ W1, const float* __restrict__ W2) {
    int i = blockIdx.x * blockDim.x + threadIdx.x;
    if (i < EMBD * EMBD) g_Wm[i] = W1[i] - W2[i];
}

// ---------------- HMMA GEMM: Y[rows,128] = X[rows,128] @ W + bias ----------------
// split-bf16: X@W ~= Xhi@Whi + Xlo@Whi + Xhi@Wlo, fp32 accum via mma.sync m16n8k16.
// W staged per CTA into smem as transposed [n][k] bf16 hi/lo (padded rows).
__global__ void __launch_bounds__(256)
gemm_mma(const float* __restrict__ X, int rows,
         const float* __restrict__ W, const float* __restrict__ bias,
         float* __restrict__ Y) {
    extern __shared__ char smem[];
    __nv_bfloat16* WH = (__nv_bfloat16*)smem;                       // 128*136*2 = 34816 B
    __nv_bfloat16* WL = (__nv_bfloat16*)(smem + 34816);             // 34816 B
    float* BS = (float*)(smem + 69632);                             // 512 B
    int tid = threadIdx.x;

    // stage W[k][n] -> WH/WL[n][k]  (transpose + hi/lo split)
    for (int i = tid; i < EMBD * EMBD; i += 256) {
        int k = i >> 7, n = i & 127;
        float w = __ldg(W + i);
        __nv_bfloat16 h = __float2bfloat16(w);
        __nv_bfloat16 l = __float2bfloat16(w - __bfloat162float(h));
        WH[n * WSTRIDE + k] = h;
        WL[n * WSTRIDE + k] = l;
    }
    if (tid < 128) BS[tid] = bias ? bias[tid] : 0.0f;
    __syncthreads();

    int lane = tid & 31, wid = tid >> 5;
    int lr = lane >> 2;   // 0..7
    int lc = lane & 3;    // 0..3

    int nstrips = (rows + 15) >> 4;
    for (int s = blockIdx.x * 8 + wid; s < nstrips; s += gridDim.x * 8) {
        int r0 = s << 4;
        int row0 = r0 + lr, row1 = r0 + lr + 8;
        bool v0 = row0 < rows, v1 = row1 < rows;
        const float* x0 = X + (size_t)row0 * EMBD + lc * 2;
        const float* x1 = X + (size_t)row1 * EMBD + lc * 2;

        // A fragments: 8 k-frags x 4 regs, hi + lo
        uint32_t AH[8][4], AL[8][4];
        #pragma unroll
        for (int kf = 0; kf < 8; kf++) {
            float2 f0 = v0 ? __ldg((const float2*)(x0 + kf * 16))     : make_float2(0.f, 0.f);
            float2 f1 = v1 ? __ldg((const float2*)(x1 + kf * 16))     : make_float2(0.f, 0.f);
            float2 f2 = v0 ? __ldg((const float2*)(x0 + kf * 16 + 8)) : make_float2(0.f, 0.f);
            float2 f3 = v1 ? __ldg((const float2*)(x1 + kf * 16 + 8)) : make_float2(0.f, 0.f);
            pack2(f0, AH[kf][0], AL[kf][0]);
            pack2(f1, AH[kf][1], AL[kf][1]);
            pack2(f2, AH[kf][2], AL[kf][2]);
            pack2(f3, AH[kf][3], AL[kf][3]);
        }

        float* y0 = Y + (size_t)row0 * EMBD;
        float* y1 = Y + (size_t)row1 * EMBD;

        #pragma unroll 4
        for (int nf = 0; nf < 16; nf++) {
            float c0 = 0.f, c1 = 0.f, c2 = 0.f, c3 = 0.f;
            const __nv_bfloat16* wh = WH + (nf * 8 + lr) * WSTRIDE + lc * 2;
            const __nv_bfloat16* wl = WL + (nf * 8 + lr) * WSTRIDE + lc * 2;
            #pragma unroll
            for (int kf = 0; kf < 8; kf++) {
                uint32_t bh0 = *(const uint32_t*)(wh + kf * 16);
                uint32_t bh1 = *(const uint32_t*)(wh + kf * 16 + 8);
                uint32_t bl0 = *(const uint32_t*)(wl + kf * 16);
                uint32_t bl1 = *(const uint32_t*)(wl + kf * 16 + 8);
                mma16816(c0, c1, c2, c3, AH[kf][0], AH[kf][1], AH[kf][2], AH[kf][3], bh0, bh1);
                mma16816(c0, c1, c2, c3, AL[kf][0], AL[kf][1], AL[kf][2], AL[kf][3], bh0, bh1);
                mma16816(c0, c1, c2, c3, AH[kf][0], AH[kf][1], AH[kf][2], AH[kf][3], bl0, bl1);
            }
            int col = nf * 8 + lc * 2;
            if (v0) {
                float2 o; o.x = c0 + BS[col]; o.y = c1 + BS[col + 1];
                *(float2*)(y0 + col) = o;
            }
            if (v1) {
                float2 o; o.x = c2 + BS[col]; o.y = c3 + BS[col + 1];
                *(float2*)(y1 + col) = o;
            }
        }
    }
}
#define GEMM_SMEM (69632 + 512)

// ---------------- EdgeConv pull: Hb[j] = sp(T1[j] + max_e T2[src[e]]), else ln2 ----------------
__global__ void k_edgeconv(const int* __restrict__ srcA, int N, float* __restrict__ hbOut) {
    int w = (blockIdx.x * blockDim.x + threadIdx.x) >> 5;
    int lane = threadIdx.x & 31;
    if (w >= N) return;
    int j = w;
    int s0 = g_rowptr[j], s1 = g_rowptr[j + 1];
    float4 out;
    if (s1 > s0) {
        float4 m = make_float4(-FLT_MAX, -FLT_MAX, -FLT_MAX, -FLT_MAX);
        for (int i = s0; i < s1; i++) {
            int e = __ldg(g_eids + i);
            int sn = __ldg(srcA + e);
            float4 v = __ldg((const float4*)(g_T2 + (size_t)sn * EMBD) + lane);
            m = max4(m, v);
        }
        float4 t = ((const float4*)(g_T1 + (size_t)j * EMBD))[lane]; // includes b_bond
        out = sp4(add4(t, m));
    } else {
        out = make_float4(LN2F, LN2F, LN2F, LN2F);
    }
    ((float4*)(g_Hb + (size_t)j * EMBD))[lane] = out;
    if (hbOut) ((float4*)(hbOut + (size_t)j * EMBD))[lane] = out;
}

// ---------------- GeneralConv pull ----------------
__global__ void k_genconv(const int* __restrict__ srcA, int N, float* __restrict__ haOut) {
    int w = (blockIdx.x * blockDim.x + threadIdx.x) >> 5;
    int lane = threadIdx.x & 31;
    if (w >= N) return;
    int j = w;
    int s0 = g_rowptr[j], s1 = g_rowptr[j + 1];
    float4 s = make_float4(0.f, 0.f, 0.f, 0.f);
    float4 cv = ((const float4*)g_cvec)[lane];
    for (int i = s0; i < s1; i++) {
        int e = __ldg(g_eids + i);
        int sn = __ldg(srcA + e);
        float4 a = __ldg((const float4*)(g_A + (size_t)sn * EMBD) + lane);
        float4 b = (e < N) ? __ldg((const float4*)(g_B + (size_t)e * EMBD) + lane) : cv;
        s = add4(s, add4(a, b));
    }
    float degf = (float)(s1 - s0);
    float4 bs = ((const float4*)g_bsum)[lane];
    float4 h = ((float4*)(g_Ha + (size_t)j * EMBD))[lane];
    s.x += degf * bs.x + h.x; s.y += degf * bs.y + h.y;
    s.z += degf * bs.z + h.z; s.w += degf * bs.w + h.w;
    float4 out = sp4(s);
    ((float4*)(g_Ha + (size_t)j * EMBD))[lane] = out;
    if (haOut) ((float4*)(haOut + (size_t)j * EMBD))[lane] = out;
}

// ---------------- constant tail of h_b output ----------------
__global__ void k_tail(float* __restrict__ outHb, int N, int E) {
    size_t idx = (size_t)blockIdx.x * blockDim.x + threadIdx.x;
    size_t tot = (size_t)(E - N) * 32;
    if (idx >= tot) return;
    float4* p = (float4*)(outHb + (size_t)N * EMBD);
    p[idx] = make_float4(LN2F, LN2F, LN2F, LN2F);
}

// ---------------- graph boundaries ----------------
__global__ void k_bounds(const int* __restrict__ batch, int N) {
    int n = blockIdx.x * blockDim.x + threadIdx.x;
    if (n >= N) return;
    int b = batch[n];
    if (n == 0 || batch[n - 1] != b) g_gs[b] = n;
    if (n == N - 1 || batch[n + 1] != b) g_ge[b] = n + 1;
}

// ---------------- pooling + readout MLP ----------------
__global__ void k_readout(const float* __restrict__ Wr1, const float* __restrict__ br1,
                          const float* __restrict__ Wr2, const float* __restrict__ br2,
                          const float* __restrict__ Wr3, const float* __restrict__ br3,
                          float* __restrict__ out) {
    __shared__ float ps[128];
    __shared__ float h1[64];
    __shared__ float h2[64];
    __shared__ float red[64];
    int g = blockIdx.x, c = threadIdx.x;
    int s = g_gs[g], e = g_ge[g];
    float acc = 0.0f;
    for (int n = s; n < e; n++) acc += g_Ha[(size_t)n * EMBD + c];
    ps[c] = acc;
    __syncthreads();
    if (c < 64) {
        float v = br1[c];
        #pragma unroll 8
        for (int k = 0; k < 128; k++) v += ps[k] * __ldg(Wr1 + k * 64 + c);
        h1[c] = spf(v);
    }
    __syncthreads();
    if (c < 64) {
        float v = br2[c];
        #pragma unroll 8
        for (int k = 0; k < 64; k++) v += h1[k] * __ldg(Wr2 + k * 64 + c);
        h2[c] = spf(v);
    }
    __syncthreads();
    if (c < 64) red[c] = h2[c] * __ldg(Wr3 + c);
    __syncthreads();
    if (c == 0) {
        float o = br3[0];
        for (int k = 0; k < 64; k++) o += red[k];
        out[g] = o;
    }
}

// ---------------- host launch ----------------
extern "C" void kernel_launch(void* const* d_in, const int* in_sizes, int n_in,
                              void* d_out_, int out_size) {
    const int*   x_ids    = (const int*)d_in[0];
    const int*   eattr    = (const int*)d_in[1];
    const int*   eidx     = (const int*)d_in[2];
    const int*   batch    = (const int*)d_in[3];
    const float* emb_atom = (const float*)d_in[4];
    const float* emb_bond = (const float*)d_in[5];
    const float* W_bond   = (const float*)d_in[6];
    const float* b_bond   = (const float*)d_in[7];
    const float* W_msg    = (const float*)d_in[8];
    const float* b_msg    = (const float*)d_in[9];
    const float* W_edge   = (const float*)d_in[10];
    const float* b_edge   = (const float*)d_in[11];
    const float* W_r1     = (const float*)d_in[12];
    const float* b_r1     = (const float*)d_in[13];
    const float* W_r2     = (const float*)d_in[14];
    const float* b_r2     = (const float*)d_in[15];
    const float* W_r3     = (const float*)d_in[16];
    const float* b_r3     = (const float*)d_in[17];

    int N = in_sizes[0];
    int E = in_sizes[1];
    if (N > NMAX || E > EMAX || N < 1 || E < N) return;

    float* d_out = (float*)d_out_;
    long long rest = (long long)out_size - (long long)EMBD * ((long long)N + (long long)E);
    int G;
    float* outHa = nullptr;
    float* outHb = nullptr;
    if (rest > 0) {
        G = (int)rest;
        outHa = d_out + G;
        outHb = d_out + (size_t)G + (size_t)N * EMBD;
    } else {
        G = out_size;
    }
    if (G > GMAXC) return;

    const int* srcA = eidx;
    const int* dstA = eidx + E;

    float *pHa, *pHb, *pT1, *pT2, *pA, *pB, *pWm;
    cudaGetSymbolAddress((void**)&pHa, g_Ha);
    cudaGetSymbolAddress((void**)&pHb, g_Hb);
    cudaGetSymbolAddress((void**)&pT1, g_T1);
    cudaGetSymbolAddress((void**)&pT2, g_T2);
    cudaGetSymbolAddress((void**)&pA,  g_A);
    cudaGetSymbolAddress((void**)&pB,  g_B);
    cudaGetSymbolAddress((void**)&pWm, g_Wm);

    cudaFuncSetAttribute(gemm_mma, cudaFuncAttributeMaxDynamicSharedMemorySize, GEMM_SMEM);

    int mNG = (N > G) ? N : G;
    k_init<<<(mNG + 255) / 256, 256>>>(N, G);
    k_deg<<<(E + 255) / 256, 256>>>(dstA, E);
    int nb = (N + 1023) / 1024;
    k_scan1<<<nb, 1024>>>(N);
    k_scan2<<<1, 32>>>(nb);
    k_scan3<<<(N + 255) / 256, 256>>>(N);
    k_cursor<<<(N + 255) / 256, 256>>>(N);
    k_fill<<<(E + 255) / 256, 256>>>(dstA, E);
    k_embed<<<(N * 32 + 255) / 256, 256>>>(x_ids, eattr, emb_atom, emb_bond, N);
    k_prep<<<1, 128>>>(W_edge, b_msg, b_edge);
    k_wprep<<<64, 256>>>(W_bond, W_bond + EMBD * EMBD);   // g_Wm = W1 - W2

    const float* W2 = W_bond + EMBD * EMBD;

    const int MMA_GRID = 296;
    int warpBlocks = (N * 32 + 255) / 256;

    for (int it = 0; it < 2; it++) {
        bool last = (it == 1);
        // T1 = Hb @ (W1 - W2) + b_bond ; T2 = Hb @ W2
        gemm_mma<<<MMA_GRID, 256, GEMM_SMEM>>>(pHb, N, pWm, b_bond, pT1);
        gemm_mma<<<MMA_GRID, 256, GEMM_SMEM>>>(pHb, N, W2, nullptr, pT2);
        k_edgeconv<<<warpBlocks, 256>>>(srcA, N, last ? outHb : nullptr);
        // B = Hb_new @ W_edge ; A = Ha_old @ W_msg
        gemm_mma<<<MMA_GRID, 256, GEMM_SMEM>>>(pHb, N, W_edge, nullptr, pB);
        gemm_mma<<<MMA_GRID, 256, GEMM_SMEM>>>(pHa, N, W_msg, nullptr, pA);
        k_genconv<<<warpBlocks, 256>>>(srcA, N, last ? outHa : nullptr);
    }

    if (outHb && E > N) {
        size_t tot = (size_t)(E - N) * 32;
        k_tail<<<(int)((tot + 255) / 256), 256>>>(outHb, N, E);
    }
    k_bounds<<<(N + 255) / 256, 256>>>(batch, N);
    k_readout<<<G, 128>>>(W_r1, b_r1, W_r2, b_r2, W_r3, b_r3, d_out);
}

// round 14
// speedup vs baseline: 1.6239x; 1.0621x over previous
#include <cuda_runtime.h>
#include <cuda_bf16.h>
#include <cfloat>
#include <math.h>
#include <cstdint>

#define EMBD 128
#define NMAX 100000
#define EMAX 400000
#define GMAXC 4096
#define LN2F 0.69314718055994530942f

// ---------------- scratch (static __device__, no allocation) ----------------
__device__ float g_Ha[(size_t)NMAX * EMBD];
__device__ float g_Hb[(size_t)NMAX * EMBD];
__device__ float g_T1[(size_t)NMAX * EMBD];
__device__ float g_T2[(size_t)NMAX * EMBD];
__device__ float g_A [(size_t)NMAX * EMBD];
__device__ float g_B [(size_t)NMAX * EMBD];
__device__ float g_Wm[EMBD * EMBD];          // W1 - W2 precomputed
__device__ int   g_deg[NMAX];
__device__ int   g_rowptr[NMAX + 1];
__device__ int   g_cursor[NMAX];
__device__ int   g_eids[EMAX];
__device__ int   g_gs[GMAXC];
__device__ int   g_ge[GMAXC];
__device__ float g_cvec[EMBD];
__device__ float g_bsum[EMBD];
__device__ int   g_bsums[256];

// ---------------- math helpers ----------------
__device__ __forceinline__ float spf(float x) {
    return fmaxf(x, 0.0f) + log1pf(expf(-fabsf(x)));
}
__device__ __forceinline__ float4 sp4(float4 v) {
    v.x = spf(v.x); v.y = spf(v.y); v.z = spf(v.z); v.w = spf(v.w); return v;
}
__device__ __forceinline__ float4 add4(float4 a, float4 b) {
    a.x += b.x; a.y += b.y; a.z += b.z; a.w += b.w; return a;
}
__device__ __forceinline__ float4 max4(float4 a, float4 b) {
    a.x = fmaxf(a.x, b.x); a.y = fmaxf(a.y, b.y);
    a.z = fmaxf(a.z, b.z); a.w = fmaxf(a.w, b.w); return a;
}

// pack a float2 into bf16x2 hi + bf16x2 lo (residual)
__device__ __forceinline__ void pack2(float2 f, uint32_t& h, uint32_t& l) {
    __nv_bfloat16 h0 = __float2bfloat16(f.x), h1 = __float2bfloat16(f.y);
    __nv_bfloat162 hh = __halves2bfloat162(h0, h1);
    __nv_bfloat162 ll = __floats2bfloat162_rn(f.x - __bfloat162float(h0),
                                              f.y - __bfloat162float(h1));
    h = *(uint32_t*)&hh;
    l = *(uint32_t*)&ll;
}
// pack two floats (hi only) into bf16x2, plus lo residual pair
__device__ __forceinline__ uint32_t packh(float a, float b) {
    __nv_bfloat162 hh = __halves2bfloat162(__float2bfloat16(a), __float2bfloat16(b));
    return *(uint32_t*)&hh;
}
__device__ __forceinline__ uint32_t packl(float a, float b) {
    float ra = a - __bfloat162float(__float2bfloat16(a));
    float rb = b - __bfloat162float(__float2bfloat16(b));
    __nv_bfloat162 ll = __floats2bfloat162_rn(ra, rb);
    return *(uint32_t*)&ll;
}

__device__ __forceinline__ void mma16816(float* c,
                                         const uint32_t* a,
                                         uint32_t b0, uint32_t b1) {
    asm volatile(
        "mma.sync.aligned.m16n8k16.row.col.f32.bf16.bf16.f32 "
        "{%0,%1,%2,%3}, {%4,%5,%6,%7}, {%8,%9}, {%0,%1,%2,%3};"
        : "+f"(c[0]), "+f"(c[1]), "+f"(c[2]), "+f"(c[3])
        : "r"(a[0]), "r"(a[1]), "r"(a[2]), "r"(a[3]), "r"(b0), "r"(b1));
}

// ---------------- setup kernels ----------------
__global__ void k_init(int N, int G) {
    int i = blockIdx.x * blockDim.x + threadIdx.x;
    if (i < N) g_deg[i] = 0;
    if (i < G) { g_gs[i] = 0; g_ge[i] = 0; }
}

__global__ void k_deg(const int* __restrict__ dst, int E) {
    int e = blockIdx.x * blockDim.x + threadIdx.x;
    if (e < E) atomicAdd(&g_deg[dst[e]], 1);
}

__global__ void k_scan1(int N) {
    __shared__ int sh[1024];
    int i = blockIdx.x * 1024 + threadIdx.x;
    int v = (i < N) ? g_deg[i] : 0;
    sh[threadIdx.x] = v;
    __syncthreads();
    for (int off = 1; off < 1024; off <<= 1) {
        int t = (threadIdx.x >= off) ? sh[threadIdx.x - off] : 0;
        __syncthreads();
        sh[threadIdx.x] += t;
        __syncthreads();
    }
    if (i < N) g_rowptr[i + 1] = sh[threadIdx.x];
    if (threadIdx.x == 1023) g_bsums[blockIdx.x] = sh[1023];
}

__global__ void k_scan2(int nb) {
    if (threadIdx.x == 0 && blockIdx.x == 0) {
        int acc = 0;
        for (int b = 0; b < nb; b++) { int t = g_bsums[b]; g_bsums[b] = acc; acc += t; }
    }
}

__global__ void k_scan3(int N) {
    int i = blockIdx.x * blockDim.x + threadIdx.x;
    if (i == 0) g_rowptr[0] = 0;
    if (i < N) g_rowptr[i + 1] += g_bsums[i >> 10];
}

__global__ void k_cursor(int N) {
    int i = blockIdx.x * blockDim.x + threadIdx.x;
    if (i < N) g_cursor[i] = g_rowptr[i];
}

__global__ void k_fill(const int* __restrict__ dst, int E) {
    int e = blockIdx.x * blockDim.x + threadIdx.x;
    if (e < E) {
        int p = atomicAdd(&g_cursor[dst[e]], 1);
        g_eids[p] = e;
    }
}

__global__ void k_embed(const int* __restrict__ xids, const int* __restrict__ eattr,
                        const float* __restrict__ embA, const float* __restrict__ embB,
                        int N) {
    int idx = blockIdx.x * blockDim.x + threadIdx.x;
    if (idx >= N * 32) return;
    int n = idx >> 5, c = idx & 31;
    float4 va = __ldg((const float4*)(embA + (size_t)xids[n] * EMBD) + c);
    ((float4*)(g_Ha + (size_t)n * EMBD))[c] = sp4(va);
    float4 vb = __ldg((const float4*)(embB + (size_t)eattr[n] * EMBD) + c);
    ((float4*)(g_Hb + (size_t)n * EMBD))[c] = sp4(vb);
}

__global__ void k_prep(const float* __restrict__ W_edge,
                       const float* __restrict__ bm, const float* __restrict__ be) {
    int c = threadIdx.x;
    float s = 0.0f;
    for (int k = 0; k < EMBD; k++) s += W_edge[k * EMBD + c];
    g_cvec[c] = LN2F * s;
    g_bsum[c] = bm[c] + be[c];
}

__global__ void k_wprep(const float* __restrict__ W1, const float* __restrict__ W2) {
    int i = blockIdx.x * blockDim.x + threadIdx.x;
    if (i < EMBD * EMBD) g_Wm[i] = W1[i] - W2[i];
}

// ---- W staging into fragment-major smem layout ----
// WF[((nf*8+kf)*32+lane)] = uint4{bh0, bh1, bl0, bl1}
// n = nf*8 + (lane>>2), k0 = kf*16 + (lane&3)*2
__device__ __forceinline__ void stage_wf(uint4* WF, const float* __restrict__ W, int tid, int nthr) {
    for (int idx = tid; idx < 4096; idx += nthr) {
        int nf = idx >> 8, kf = (idx >> 5) & 7, lane = idx & 31;
        int n = nf * 8 + (lane >> 2);
        int k0 = kf * 16 + (lane & 3) * 2;
        float w0 = __ldg(W + k0 * EMBD + n);
        float w1 = __ldg(W + (k0 + 1) * EMBD + n);
        float w8 = __ldg(W + (k0 + 8) * EMBD + n);
        float w9 = __ldg(W + (k0 + 9) * EMBD + n);
        uint4 v;
        v.x = packh(w0, w1);
        v.y = packh(w8, w9);
        v.z = packl(w0, w1);
        v.w = packl(w8, w9);
        WF[idx] = v;
    }
}

// build A fragments (hi/lo) for one 16-row strip
__device__ __forceinline__ void build_afrag(const float* __restrict__ X, int rows,
                                            int r0, int lr, int lc,
                                            uint32_t AH[8][4], uint32_t AL[8][4],
                                            bool& v0, bool& v1) {
    int row0 = r0 + lr, row1 = r0 + lr + 8;
    v0 = row0 < rows; v1 = row1 < rows;
    const float* x0 = X + (size_t)row0 * EMBD + lc * 2;
    const float* x1 = X + (size_t)row1 * EMBD + lc * 2;
    #pragma unroll
    for (int kf = 0; kf < 8; kf++) {
        float2 f0 = v0 ? __ldg((const float2*)(x0 + kf * 16))     : make_float2(0.f, 0.f);
        float2 f1 = v1 ? __ldg((const float2*)(x1 + kf * 16))     : make_float2(0.f, 0.f);
        float2 f2 = v0 ? __ldg((const float2*)(x0 + kf * 16 + 8)) : make_float2(0.f, 0.f);
        float2 f3 = v1 ? __ldg((const float2*)(x1 + kf * 16 + 8)) : make_float2(0.f, 0.f);
        pack2(f0, AH[kf][0], AL[kf][0]);
        pack2(f1, AH[kf][1], AL[kf][1]);
        pack2(f2, AH[kf][2], AL[kf][2]);
        pack2(f3, AH[kf][3], AL[kf][3]);
    }
}

// ---------------- single-output HMMA GEMM (66 KB smem -> 3 CTAs/SM) ----------------
__global__ void __launch_bounds__(256)
gemm_mma(const float* __restrict__ X, int rows,
         const float* __restrict__ W, const float* __restrict__ bias,
         float* __restrict__ Y) {
    extern __shared__ char smem[];
    uint4* WF = (uint4*)smem;                 // 65536 B
    float* BS = (float*)(smem + 65536);       // 512 B
    int tid = threadIdx.x;

    stage_wf(WF, W, tid, 256);
    if (tid < 128) BS[tid] = bias ? bias[tid] : 0.0f;
    __syncthreads();

    int lane = tid & 31, wid = tid >> 5;
    int lr = lane >> 2, lc = lane & 3;

    int nstrips = (rows + 15) >> 4;
    for (int s = blockIdx.x * 8 + wid; s < nstrips; s += gridDim.x * 8) {
        int r0 = s << 4;
        uint32_t AH[8][4], AL[8][4];
        bool v0, v1;
        build_afrag(X, rows, r0, lr, lc, AH, AL, v0, v1);

        float* y0 = Y + (size_t)(r0 + lr) * EMBD;
        float* y1 = Y + (size_t)(r0 + lr + 8) * EMBD;

        #pragma unroll 2
        for (int nf = 0; nf < 16; nf++) {
            float ch[4] = {0,0,0,0}, cl[4] = {0,0,0,0}, cw[4] = {0,0,0,0};
            const uint4* wf = WF + (nf * 8) * 32 + lane;
            #pragma unroll
            for (int kf = 0; kf < 8; kf++) {
                uint4 f = wf[kf * 32];
                mma16816(ch, AH[kf], f.x, f.y);   // hi @ Whi
                mma16816(cl, AL[kf], f.x, f.y);   // lo @ Whi
                mma16816(cw, AH[kf], f.z, f.w);   // hi @ Wlo
            }
            int col = nf * 8 + lc * 2;
            if (v0) {
                float2 o;
                o.x = ch[0] + cl[0] + cw[0] + BS[col];
                o.y = ch[1] + cl[1] + cw[1] + BS[col + 1];
                *(float2*)(y0 + col) = o;
            }
            if (v1) {
                float2 o;
                o.x = ch[2] + cl[2] + cw[2] + BS[col];
                o.y = ch[3] + cl[3] + cw[3] + BS[col + 1];
                *(float2*)(y1 + col) = o;
            }
        }
    }
}
#define GEMM_SMEM (65536 + 512)

// ---------------- dual-output HMMA GEMM: Ya = X@Wa + biasA ; Yb = X@Wb ----------------
// shares A-fragment build + X reads between the two GEMMs (131 KB smem -> 1 CTA/SM)
__global__ void __launch_bounds__(256)
gemm_dual(const float* __restrict__ X, int rows,
          const float* __restrict__ Wa, const float* __restrict__ biasA, float* __restrict__ Ya,
          const float* __restrict__ Wb, float* __restrict__ Yb) {
    extern __shared__ char smem[];
    uint4* WFa = (uint4*)smem;                  // 65536 B
    uint4* WFb = (uint4*)(smem + 65536);        // 65536 B
    float* BS  = (float*)(smem + 131072);       // 512 B
    int tid = threadIdx.x;

    stage_wf(WFa, Wa, tid, 256);
    stage_wf(WFb, Wb, tid, 256);
    if (tid < 128) BS[tid] = biasA ? biasA[tid] : 0.0f;
    __syncthreads();

    int lane = tid & 31, wid = tid >> 5;
    int lr = lane >> 2, lc = lane & 3;

    int nstrips = (rows + 15) >> 4;
    for (int s = blockIdx.x * 8 + wid; s < nstrips; s += gridDim.x * 8) {
        int r0 = s << 4;
        uint32_t AH[8][4], AL[8][4];
        bool v0, v1;
        build_afrag(X, rows, r0, lr, lc, AH, AL, v0, v1);

        float* ya0 = Ya + (size_t)(r0 + lr) * EMBD;
        float* ya1 = Ya + (size_t)(r0 + lr + 8) * EMBD;
        float* yb0 = Yb + (size_t)(r0 + lr) * EMBD;
        float* yb1 = Yb + (size_t)(r0 + lr + 8) * EMBD;

        for (int nf = 0; nf < 16; nf++) {
            float ah[4] = {0,0,0,0}, al[4] = {0,0,0,0}, aw[4] = {0,0,0,0};
            float bh[4] = {0,0,0,0}, bl[4] = {0,0,0,0}, bw[4] = {0,0,0,0};
            const uint4* wfa = WFa + (nf * 8) * 32 + lane;
            const uint4* wfb = WFb + (nf * 8) * 32 + lane;
            #pragma unroll
            for (int kf = 0; kf < 8; kf++) {
                uint4 fa = wfa[kf * 32];
                uint4 fb = wfb[kf * 32];
                mma16816(ah, AH[kf], fa.x, fa.y);
                mma16816(bh, AH[kf], fb.x, fb.y);
                mma16816(al, AL[kf], fa.x, fa.y);
                mma16816(bl, AL[kf], fb.x, fb.y);
                mma16816(aw, AH[kf], fa.z, fa.w);
                mma16816(bw, AH[kf], fb.z, fb.w);
            }
            int col = nf * 8 + lc * 2;
            if (v0) {
                float2 oa, ob;
                oa.x = ah[0] + al[0] + aw[0] + BS[col];
                oa.y = ah[1] + al[1] + aw[1] + BS[col + 1];
                ob.x = bh[0] + bl[0] + bw[0];
                ob.y = bh[1] + bl[1] + bw[1];
                *(float2*)(ya0 + col) = oa;
                *(float2*)(yb0 + col) = ob;
            }
            if (v1) {
                float2 oa, ob;
                oa.x = ah[2] + al[2] + aw[2] + BS[col];
                oa.y = ah[3] + al[3] + aw[3] + BS[col + 1];
                ob.x = bh[2] + bl[2] + bw[2];
                ob.y = bh[3] + bl[3] + bw[3];
                *(float2*)(ya1 + col) = oa;
                *(float2*)(yb1 + col) = ob;
            }
        }
    }
}
#define DUAL_SMEM (131072 + 512)

// ---------------- EdgeConv pull: Hb[j] = sp(T1[j] + max_e T2[src[e]]), else ln2 ----------------
__global__ void k_edgeconv(const int* __restrict__ srcA, int N, float* __restrict__ hbOut) {
    int w = (blockIdx.x * blockDim.x + threadIdx.x) >> 5;
    int lane = threadIdx.x & 31;
    if (w >= N) return;
    int j = w;
    int s0 = g_rowptr[j], s1 = g_rowptr[j + 1];
    float4 out;
    if (s1 > s0) {
        float4 m = make_float4(-FLT_MAX, -FLT_MAX, -FLT_MAX, -FLT_MAX);
        for (int i = s0; i < s1; i++) {
            int e = __ldg(g_eids + i);
            int sn = __ldg(srcA + e);
            float4 v = __ldg((const float4*)(g_T2 + (size_t)sn * EMBD) + lane);
            m = max4(m, v);
        }
        float4 t = ((const float4*)(g_T1 + (size_t)j * EMBD))[lane]; // includes b_bond
        out = sp4(add4(t, m));
    } else {
        out = make_float4(LN2F, LN2F, LN2F, LN2F);
    }
    ((float4*)(g_Hb + (size_t)j * EMBD))[lane] = out;
    if (hbOut) ((float4*)(hbOut + (size_t)j * EMBD))[lane] = out;
}

// ---------------- GeneralConv pull ----------------
__global__ void k_genconv(const int* __restrict__ srcA, int N, float* __restrict__ haOut) {
    int w = (blockIdx.x * blockDim.x + threadIdx.x) >> 5;
    int lane = threadIdx.x & 31;
    if (w >= N) return;
    int j = w;
    int s0 = g_rowptr[j], s1 = g_rowptr[j + 1];
    float4 s = make_float4(0.f, 0.f, 0.f, 0.f);
    float4 cv = ((const float4*)g_cvec)[lane];
    for (int i = s0; i < s1; i++) {
        int e = __ldg(g_eids + i);
        int sn = __ldg(srcA + e);
        float4 a = __ldg((const float4*)(g_A + (size_t)sn * EMBD) + lane);
        float4 b = (e < N) ? __ldg((const float4*)(g_B + (size_t)e * EMBD) + lane) : cv;
        s = add4(s, add4(a, b));
    }
    float degf = (float)(s1 - s0);
    float4 bs = ((const float4*)g_bsum)[lane];
    float4 h = ((float4*)(g_Ha + (size_t)j * EMBD))[lane];
    s.x += degf * bs.x + h.x; s.y += degf * bs.y + h.y;
    s.z += degf * bs.z + h.z; s.w += degf * bs.w + h.w;
    float4 out = sp4(s);
    ((float4*)(g_Ha + (size_t)j * EMBD))[lane] = out;
    if (haOut) ((float4*)(haOut + (size_t)j * EMBD))[lane] = out;
}

// ---------------- constant tail of h_b output ----------------
__global__ void k_tail(float* __restrict__ outHb, int N, int E) {
    size_t idx = (size_t)blockIdx.x * blockDim.x + threadIdx.x;
    size_t tot = (size_t)(E - N) * 32;
    if (idx >= tot) return;
    float4* p = (float4*)(outHb + (size_t)N * EMBD);
    p[idx] = make_float4(LN2F, LN2F, LN2F, LN2F);
}

// ---------------- graph boundaries ----------------
__global__ void k_bounds(const int* __restrict__ batch, int N) {
    int n = blockIdx.x * blockDim.x + threadIdx.x;
    if (n >= N) return;
    int b = batch[n];
    if (n == 0 || batch[n - 1] != b) g_gs[b] = n;
    if (n == N - 1 || batch[n + 1] != b) g_ge[b] = n + 1;
}

// ---------------- pooling + readout MLP ----------------
__global__ void k_readout(const float* __restrict__ Wr1, const float* __restrict__ br1,
                          const float* __restrict__ Wr2, const float* __restrict__ br2,
                          const float* __restrict__ Wr3, const float* __restrict__ br3,
                          float* __restrict__ out) {
    __shared__ float ps[128];
    __shared__ float h1[64];
    __shared__ float h2[64];
    __shared__ float red[64];
    int g = blockIdx.x, c = threadIdx.x;
    int s = g_gs[g], e = g_ge[g];
    float acc = 0.0f;
    for (int n = s; n < e; n++) acc += g_Ha[(size_t)n * EMBD + c];
    ps[c] = acc;
    __syncthreads();
    if (c < 64) {
        float v = br1[c];
        #pragma unroll 8
        for (int k = 0; k < 128; k++) v += ps[k] * __ldg(Wr1 + k * 64 + c);
        h1[c] = spf(v);
    }
    __syncthreads();
    if (c < 64) {
        float v = br2[c];
        #pragma unroll 8
        for (int k = 0; k < 64; k++) v += h1[k] * __ldg(Wr2 + k * 64 + c);
        h2[c] = spf(v);
    }
    __syncthreads();
    if (c < 64) red[c] = h2[c] * __ldg(Wr3 + c);
    __syncthreads();
    if (c == 0) {
        float o = br3[0];
        for (int k = 0; k < 64; k++) o += red[k];
        out[g] = o;
    }
}

// ---------------- host launch ----------------
extern "C" void kernel_launch(void* const* d_in, const int* in_sizes, int n_in,
                              void* d_out_, int out_size) {
    const int*   x_ids    = (const int*)d_in[0];
    const int*   eattr    = (const int*)d_in[1];
    const int*   eidx     = (const int*)d_in[2];
    const int*   batch    = (const int*)d_in[3];
    const float* emb_atom = (const float*)d_in[4];
    const float* emb_bond = (const float*)d_in[5];
    const float* W_bond   = (const float*)d_in[6];
    const float* b_bond   = (const float*)d_in[7];
    const float* W_msg    = (const float*)d_in[8];
    const float* b_msg    = (const float*)d_in[9];
    const float* W_edge   = (const float*)d_in[10];
    const float* b_edge   = (const float*)d_in[11];
    const float* W_r1     = (const float*)d_in[12];
    const float* b_r1     = (const float*)d_in[13];
    const float* W_r2     = (const float*)d_in[14];
    const float* b_r2     = (const float*)d_in[15];
    const float* W_r3     = (const float*)d_in[16];
    const float* b_r3     = (const float*)d_in[17];

    int N = in_sizes[0];
    int E = in_sizes[1];
    if (N > NMAX || E > EMAX || N < 1 || E < N) return;

    float* d_out = (float*)d_out_;
    long long rest = (long long)out_size - (long long)EMBD * ((long long)N + (long long)E);
    int G;
    float* outHa = nullptr;
    float* outHb = nullptr;
    if (rest > 0) {
        G = (int)rest;
        outHa = d_out + G;
        outHb = d_out + (size_t)G + (size_t)N * EMBD;
    } else {
        G = out_size;
    }
    if (G > GMAXC) return;

    const int* srcA = eidx;
    const int* dstA = eidx + E;

    float *pHa, *pHb, *pT1, *pT2, *pA, *pB, *pWm;
    cudaGetSymbolAddress((void**)&pHa, g_Ha);
    cudaGetSymbolAddress((void**)&pHb, g_Hb);
    cudaGetSymbolAddress((void**)&pT1, g_T1);
    cudaGetSymbolAddress((void**)&pT2, g_T2);
    cudaGetSymbolAddress((void**)&pA,  g_A);
    cudaGetSymbolAddress((void**)&pB,  g_B);
    cudaGetSymbolAddress((void**)&pWm, g_Wm);

    cudaFuncSetAttribute(gemm_mma, cudaFuncAttributeMaxDynamicSharedMemorySize, GEMM_SMEM);
    cudaFuncSetAttribute(gemm_dual, cudaFuncAttributeMaxDynamicSharedMemorySize, DUAL_SMEM);

    const float* W2 = W_bond + EMBD * EMBD;
    const int MMA_GRID = 444;    // 3 CTAs/SM at 66 KB smem
    const int DUAL_GRID = 148;   // 1 CTA/SM at 131 KB smem
    int warpBlocks = (N * 32 + 255) / 256;
    int mNG = (N > G) ? N : G;
    int nb = (N + 1023) / 1024;

    // launch order chosen so the dual GEMM is launch index 5 -> captured by ncu -s 5 -c 1
    k_init<<<(mNG + 255) / 256, 256>>>(N, G);                                   // 0
    k_deg<<<(E + 255) / 256, 256>>>(dstA, E);                                   // 1
    k_embed<<<(N * 32 + 255) / 256, 256>>>(x_ids, eattr, emb_atom, emb_bond, N);// 2
    k_prep<<<1, 128>>>(W_edge, b_msg, b_edge);                                  // 3
    k_wprep<<<64, 256>>>(W_bond, W2);                                           // 4
    // iteration 1: T1 = Hb@(W1-W2)+b_bond ; T2 = Hb@W2 (fused)
    gemm_dual<<<DUAL_GRID, 256, DUAL_SMEM>>>(pHb, N, pWm, b_bond, pT1, W2, pT2);// 5 <- profiled
    k_scan1<<<nb, 1024>>>(N);                                                   // 6
    k_scan2<<<1, 32>>>(nb);
    k_scan3<<<(N + 255) / 256, 256>>>(N);
    k_cursor<<<(N + 255) / 256, 256>>>(N);
    k_fill<<<(E + 255) / 256, 256>>>(dstA, E);
    k_edgeconv<<<warpBlocks, 256>>>(srcA, N, nullptr);
    gemm_mma<<<MMA_GRID, 256, GEMM_SMEM>>>(pHb, N, W_edge, nullptr, pB);
    gemm_mma<<<MMA_GRID, 256, GEMM_SMEM>>>(pHa, N, W_msg, nullptr, pA);
    k_genconv<<<warpBlocks, 256>>>(srcA, N, nullptr);
    // iteration 2
    gemm_dual<<<DUAL_GRID, 256, DUAL_SMEM>>>(pHb, N, pWm, b_bond, pT1, W2, pT2);
    k_edgeconv<<<warpBlocks, 256>>>(srcA, N, outHb);
    gemm_mma<<<MMA_GRID, 256, GEMM_SMEM>>>(pHb, N, W_edge, nullptr, pB);
    gemm_mma<<<MMA_GRID, 256, GEMM_SMEM>>>(pHa, N, W_msg, nullptr, pA);
    k_genconv<<<warpBlocks, 256>>>(srcA, N, outHa);

    if (outHb && E > N) {
        size_t tot = (size_t)(E - N) * 32;
        k_tail<<<(int)((tot + 255) / 256), 256>>>(outHb, N, E);
    }
    k_bounds<<<(N + 255) / 256, 256>>>(batch, N);
    k_readout<<<G, 128>>>(W_r1, b_r1, W_r2, b_r2, W_r3, b_r3, d_out);
}